// round 4
// baseline (speedup 1.0000x reference)
#include <cuda_runtime.h>

#define BATCH 8
#define DIM 256
#define SEQ 16384
#define KK 3
#define HID 85
#define OUTC (DIM*KK)
#define BN_EPS 1e-5f
#define FULLM 0xffffffffu

// Scratch (device globals — no allocation allowed)
__device__ float g_pooled[BATCH * DIM];
__device__ float g_w[BATCH * OUTC];

// ---------------------------------------------------------------------------
// Kernel 1: mean over seq for each (b, c) row. grid=(DIM, BATCH), block=512.
// 2 batches of 4 front-batched float4 loads (MLP_p1=4 to limit cross-CTA
// L1tex queue contention).
// ---------------------------------------------------------------------------
__global__ void pool_kernel(const float* __restrict__ x) {
    const int c = blockIdx.x;
    const int b = blockIdx.y;
    const size_t rowoff = ((size_t)b * DIM + c) * SEQ;
    const float4* row = (const float4*)(x + rowoff);

    float s = 0.f;
    #pragma unroll
    for (int g = 0; g < 2; g++) {
        float4 v[4];
        #pragma unroll
        for (int j = 0; j < 4; j++)
            v[j] = row[threadIdx.x + (g * 4 + j) * 512];
        #pragma unroll
        for (int j = 0; j < 4; j++)
            s += (v[j].x + v[j].y) + (v[j].z + v[j].w);
    }

    #pragma unroll
    for (int off = 16; off > 0; off >>= 1)
        s += __shfl_down_sync(FULLM, s, off);

    __shared__ float sm[16];
    if ((threadIdx.x & 31) == 0) sm[threadIdx.x >> 5] = s;
    __syncthreads();
    if (threadIdx.x < 16) {
        float t = sm[threadIdx.x];
        #pragma unroll
        for (int off = 8; off > 0; off >>= 1)
            t += __shfl_down_sync(0xffffu, t, off);
        if (threadIdx.x == 0) g_pooled[b * DIM + c] = t * (1.f / SEQ);
    }
}

// ---------------------------------------------------------------------------
// Kernel 2: tiny MLP. grid=(4, BATCH), block=256.
// ---------------------------------------------------------------------------
__global__ void mlp_kernel(const float* __restrict__ w1,
                           const float* __restrict__ gamma,
                           const float* __restrict__ beta,
                           const float* __restrict__ mean,
                           const float* __restrict__ var,
                           const float* __restrict__ w2,
                           const float* __restrict__ b2) {
    const int b = blockIdx.y;
    const int chunk = blockIdx.x;          // 0..3, 192 outputs each
    const int tid = threadIdx.x;

    __shared__ float ps[DIM];
    __shared__ float ys[HID];

    ps[tid] = g_pooled[b * DIM + tid];
    __syncthreads();

    if (tid < HID) {
        const float* wr = w1 + tid * DIM;
        float acc = 0.f;
        #pragma unroll 8
        for (int c = 0; c < DIM; c++) acc = fmaf(wr[c], ps[c], acc);
        float v = (acc - mean[tid]) * (gamma[tid] * rsqrtf(var[tid] + BN_EPS)) + beta[tid];
        ys[tid] = fmaxf(v, 0.f);
    }
    __syncthreads();

    const int o = chunk * 192 + tid;
    if (tid < 192) {
        const float* wr = w2 + o * HID;
        float acc = b2[o];
        #pragma unroll 5
        for (int h = 0; h < HID; h++) acc = fmaf(wr[h], ys[h], acc);
        g_w[b * OUTC + o] = acc;
    }
}

// ---------------------------------------------------------------------------
// Kernel 3: depthwise 3-tap conv, pad=1, + bias.
// grid=(2, DIM, BATCH), block=512. Each thread: 4 front-batched float4 loads
// (strided by 512 f4 within the half-row). Halo via warp shuffle.
// Reversed traversal (conv starts on the tail of x, freshest in L2).
// out written WRITE-THROUGH (__stwt): no L2 allocation for the output stream,
// so L2 stays dedicated to x lines left by pool.
// ---------------------------------------------------------------------------
__global__ void conv_kernel(const float* __restrict__ x,
                            const float* __restrict__ bias,
                            float* __restrict__ out) {
    const int b = (BATCH - 1) - blockIdx.z;
    const int c = (DIM - 1) - blockIdx.y;
    const int half = 1 - blockIdx.x;                 // 0 or 1 (reversed)
    const int tid = threadIdx.x;
    const int lane = tid & 31;
    const size_t rowoff = ((size_t)b * DIM + c) * SEQ;
    const int base = half * 2048;                    // f4 index base of half-row

    const float w0  = g_w[b * OUTC + c * KK + 0];
    const float w1v = g_w[b * OUTC + c * KK + 1];
    const float w2v = g_w[b * OUTC + c * KK + 2];
    const float bb  = __ldg(bias + c);

    int t[4];
    float4 v[4];
    #pragma unroll
    for (int j = 0; j < 4; j++) {
        t[j] = (base + j * 512 + tid) * 4;           // float index of segment j
        v[j] = *(const float4*)(x + rowoff + t[j]);
    }

    #pragma unroll
    for (int j = 0; j < 4; j++) {
        float xl = __shfl_up_sync(FULLM, v[j].w, 1);
        float xr = __shfl_down_sync(FULLM, v[j].x, 1);
        if (lane == 0)
            xl = (t[j] == 0) ? 0.f : __ldg(x + rowoff + t[j] - 1);
        if (lane == 31)
            xr = (t[j] + 4 >= SEQ) ? 0.f : __ldg(x + rowoff + t[j] + 4);

        float4 o;
        o.x = fmaf(w0, xl,     fmaf(w1v, v[j].x, fmaf(w2v, v[j].y, bb)));
        o.y = fmaf(w0, v[j].x, fmaf(w1v, v[j].y, fmaf(w2v, v[j].z, bb)));
        o.z = fmaf(w0, v[j].y, fmaf(w1v, v[j].z, fmaf(w2v, v[j].w, bb)));
        o.w = fmaf(w0, v[j].z, fmaf(w1v, v[j].w, fmaf(w2v, xr,     bb)));

        __stwt((float4*)(out + rowoff + t[j]), o);
    }
}

// ---------------------------------------------------------------------------
// Launch. Inputs (metadata order): x, w1, bn_gamma, bn_beta, bn_mean, bn_var,
// w2, b2, bias. Output: fp32 [8, 256, 16384].
// ---------------------------------------------------------------------------
extern "C" void kernel_launch(void* const* d_in, const int* in_sizes, int n_in,
                              void* d_out, int out_size) {
    const float* x     = (const float*)d_in[0];
    const float* w1    = (const float*)d_in[1];
    const float* gamma = (const float*)d_in[2];
    const float* beta  = (const float*)d_in[3];
    const float* mean  = (const float*)d_in[4];
    const float* var   = (const float*)d_in[5];
    const float* w2    = (const float*)d_in[6];
    const float* b2    = (const float*)d_in[7];
    const float* bias  = (const float*)d_in[8];
    float* out = (float*)d_out;

    dim3 pg(DIM, BATCH);
    pool_kernel<<<pg, 512>>>(x);

    dim3 mg(4, BATCH);
    mlp_kernel<<<mg, 256>>>(w1, gamma, beta, mean, var, w2, b2);

    dim3 cg(2, DIM, BATCH);
    conv_kernel<<<cg, 512>>>(x, bias, out);
}